// round 15
// baseline (speedup 1.0000x reference)
#include <cuda_runtime.h>
#include <cuda_fp16.h>
#include <mma.h>
#include <cstdint>
#include <math.h>

using namespace nvcuda;

#define B_  2
#define T_  2048
#define C_  768
#define H_  12
#define HD_ 64
#define M_  (B_*T_)   // 4096

// Scratch (allocations forbidden -> device globals)
__device__ __half g_hx[M_*C_];
__device__ __half g_hq[M_*C_];
__device__ __half g_hk[M_*C_];   // COMPACTED: batch b rows [0, nvalid[b]) at offset b*T_
__device__ __half g_hv[M_*C_];   // COMPACTED likewise
__device__ __half g_hy[M_*C_];
__device__ __half g_hwq[C_*C_];
__device__ __half g_hwk[C_*C_];
__device__ __half g_hwv[C_*C_];
__device__ __half g_hwp[C_*C_];
__device__ int    g_pos[M_];     // compact dst position per (b,t); -1 if masked
__device__ int    g_nvalid[B_];  // valid-key count per batch

// ---------------------------------------------------------------------------
__device__ __forceinline__ uint32_t smem_u32(const void* p) {
    uint32_t r;
    asm("{ .reg .u64 t; cvta.to.shared.u64 t, %1; cvt.u32.u64 %0, t; }"
        : "=r"(r) : "l"(p));
    return r;
}
__device__ __forceinline__ void cp16(uint32_t dst, const void* src) {
    asm volatile("cp.async.ca.shared.global [%0], [%1], 16;" :: "r"(dst), "l"(src));
}
#define CP_COMMIT() asm volatile("cp.async.commit_group;" ::: "memory")
#define CP_WAIT(N)  asm volatile("cp.async.wait_group %0;" :: "n"(N) : "memory")

__device__ __forceinline__ void ldm4(uint32_t r[4], uint32_t a) {
    asm volatile("ldmatrix.sync.aligned.m8n8.x4.shared.b16 {%0,%1,%2,%3}, [%4];"
        : "=r"(r[0]), "=r"(r[1]), "=r"(r[2]), "=r"(r[3]) : "r"(a));
}
__device__ __forceinline__ void ldm4t(uint32_t r[4], uint32_t a) {
    asm volatile("ldmatrix.sync.aligned.m8n8.x4.trans.shared.b16 {%0,%1,%2,%3}, [%4];"
        : "=r"(r[0]), "=r"(r[1]), "=r"(r[2]), "=r"(r[3]) : "r"(a));
}
__device__ __forceinline__ void mma_f16(float d[4], const uint32_t a[4], const uint32_t b[2]) {
    asm volatile(
        "mma.sync.aligned.m16n8k16.row.col.f32.f16.f16.f32 "
        "{%0,%1,%2,%3}, {%4,%5,%6,%7}, {%8,%9}, {%0,%1,%2,%3};"
        : "+f"(d[0]), "+f"(d[1]), "+f"(d[2]), "+f"(d[3])
        : "r"(a[0]), "r"(a[1]), "r"(a[2]), "r"(a[3]), "r"(b[0]), "r"(b[1]));
}
__device__ __forceinline__ uint32_t pack_h2(float p0, float p1) {
    uint32_t u;
    asm("cvt.rn.f16x2.f32 %0, %1, %2;" : "=r"(u) : "f"(p1), "f"(p0));
    return u;
}

// ---------------------------------------------------------------------------
// fused f32 -> f16 convert: x + 4 weight matrices in ONE launch
// ---------------------------------------------------------------------------
#define X4_ (M_*C_/4)
#define W4_ (C_*C_/4)
#define N4TOT_ (X4_ + 4*W4_)

__global__ void f2h5(const float* __restrict__ x,
                     const float* __restrict__ w0, const float* __restrict__ w1,
                     const float* __restrict__ w2, const float* __restrict__ w3)
{
    int i = blockIdx.x * blockDim.x + threadIdx.x;
    if (i >= N4TOT_) return;
    const float* s;
    __half* d;
    int k;
    if (i < X4_) { s = x; d = g_hx; k = i; }
    else {
        int j = i - X4_;
        int seg = j / W4_;
        k = j - seg * W4_;
        s = (seg == 0) ? w0 : (seg == 1) ? w1 : (seg == 2) ? w2 : w3;
        d = (seg == 0) ? g_hwq : (seg == 1) ? g_hwk : (seg == 2) ? g_hwv : g_hwp;
    }
    float4 v = ((const float4*)s)[k];
    ((__half2*)d)[2 * k + 0] = __floats2half2_rn(v.x, v.y);
    ((__half2*)d)[2 * k + 1] = __floats2half2_rn(v.z, v.w);
}

// ---------------------------------------------------------------------------
// Deterministic mask scan: per (b,t) compact position g_pos (-1 if masked)
// and per-batch count g_nvalid. One block per batch, 128 threads x 16 keys.
// ---------------------------------------------------------------------------
__global__ void scan_mask(const int* __restrict__ mask)
{
    int b = blockIdx.x;
    int t = threadIdx.x;            // 0..127
    int lane = t & 31, wid = t >> 5;
    const int* mb = mask + b * T_;

    int base = t * 16;
    int v[16];
    int loc = 0;
    #pragma unroll
    for (int j = 0; j < 16; j++) { v[j] = (mb[base + j] != 0); loc += v[j]; }

    int x = loc;
    #pragma unroll
    for (int off = 1; off < 32; off <<= 1) {
        int y = __shfl_up_sync(0xffffffffu, x, off);
        if (lane >= off) x += y;
    }
    __shared__ int wsum[4];
    if (lane == 31) wsum[wid] = x;
    __syncthreads();
    int woff = 0;
    #pragma unroll
    for (int i = 0; i < 4; i++) if (i < wid) woff += wsum[i];
    int pos = woff + x - loc;

    #pragma unroll
    for (int j = 0; j < 16; j++) {
        g_pos[b * T_ + base + j] = v[j] ? pos : -1;
        pos += v[j];
    }

    if (t == 0) g_nvalid[b] = wsum[0] + wsum[1] + wsum[2] + wsum[3];
}

// ===========================================================================
// fp16 WMMA GEMM (R8 mainloop): CTA 256x128, BK=64, 8 warps, warp tile 64x64.
// Epilogue: if posmap != nullptr and which != 0 (K/V outputs), each row is
// scattered to its compacted position (masked rows skipped).
// ===========================================================================
#define LDH  72
#define LDC_ 132
#define NCH  12

#define G_A_SZ (256*LDH*2)
#define G_W_SZ (128*LDH*2)
#define G_BUF  (G_A_SZ + G_W_SZ)
#define SMEM_GEMM_ (2*G_BUF)

__global__ __launch_bounds__(256) void gemm_h(
    const __half* __restrict__ A,
    const __half* __restrict__ W0, const __half* __restrict__ W1, const __half* __restrict__ W2,
    const float* __restrict__ b0, const float* __restrict__ b1, const float* __restrict__ b2,
    __half* __restrict__ C0, __half* __restrict__ C1, __half* __restrict__ C2,
    float* __restrict__ CF, const int* __restrict__ posmap)
{
    extern __shared__ char smc[];
    float* St = (float*)smc;
    const uint32_t sb = smem_u32(smc);

    const int tid = threadIdx.x;
    const int wid = tid >> 5;
    const int warp_m = wid & 3;
    const int warp_n = wid >> 2;

    const int m0 = blockIdx.x * 256;
    const int which = blockIdx.y / 6;
    const int n0 = (blockIdx.y % 6) * 128;
    const __half* W   = (which == 0) ? W0 : (which == 1) ? W1 : W2;
    const float* bias = (which == 0) ? b0 : (which == 1) ? b1 : b2;
    __half*      Cm   = (which == 0) ? C0 : (which == 1) ? C1 : C2;
    const bool   comp = (posmap != nullptr) && (which != 0);

    const __half* Arow = A + (size_t)m0 * C_;
    const __half* Wrow = W + (size_t)n0 * C_;

    wmma::fragment<wmma::accumulator, 16, 16, 16, float> acc[4][4];
    #pragma unroll
    for (int i = 0; i < 4; i++)
        #pragma unroll
        for (int j = 0; j < 4; j++)
            wmma::fill_fragment(acc[i][j], 0.0f);

    auto stage = [&](int buf, int k0) {
        uint32_t Ad = sb + (buf ? (uint32_t)G_BUF : 0u);
        uint32_t Wd = Ad + (uint32_t)G_A_SZ;
        #pragma unroll
        for (int e = 0; e < 8; e++) {
            int lin = e * 256 + tid;
            int row = lin >> 3, c8 = lin & 7;
            cp16(Ad + (uint32_t)(row * LDH + c8 * 8) * 2,
                 Arow + (size_t)row * C_ + k0 + c8 * 8);
        }
        #pragma unroll
        for (int e = 0; e < 4; e++) {
            int lin = e * 256 + tid;
            int row = lin >> 3, c8 = lin & 7;
            cp16(Wd + (uint32_t)(row * LDH + c8 * 8) * 2,
                 Wrow + (size_t)row * C_ + k0 + c8 * 8);
        }
    };

    stage(0, 0);
    CP_COMMIT();

    for (int c = 0; c < NCH; c++) {
        const int b = c & 1;
        if (c < NCH - 1) { stage(b ^ 1, (c + 1) * 64); CP_COMMIT(); CP_WAIT(1); }
        else             { CP_WAIT(0); }
        __syncthreads();

        const __half* Ab = (const __half*)(smc + (b ? G_BUF : 0));
        const __half* Wb = (const __half*)((const char*)Ab + G_A_SZ);
        #pragma unroll
        for (int ks = 0; ks < 4; ks++) {
            wmma::fragment<wmma::matrix_a, 16, 16, 16, __half, wmma::row_major> af[4];
            #pragma unroll
            for (int i = 0; i < 4; i++)
                wmma::load_matrix_sync(af[i], Ab + (warp_m * 64 + i * 16) * LDH + ks * 16, LDH);
            #pragma unroll
            for (int j = 0; j < 4; j++) {
                wmma::fragment<wmma::matrix_b, 16, 16, 16, __half, wmma::col_major> bf;
                wmma::load_matrix_sync(bf, Wb + (warp_n * 64 + j * 16) * LDH + ks * 16, LDH);
                #pragma unroll
                for (int i = 0; i < 4; i++)
                    wmma::mma_sync(acc[i][j], af[i], bf, acc[i][j]);
            }
        }
        __syncthreads();
    }

    #pragma unroll
    for (int p = 0; p < 2; p++) {
        if ((warp_m >> 1) == p) {
            int lm = (warp_m & 1) * 64;
            #pragma unroll
            for (int i = 0; i < 4; i++)
                #pragma unroll
                for (int j = 0; j < 4; j++)
                    wmma::store_matrix_sync(
                        St + (lm + i * 16) * LDC_ + warp_n * 64 + j * 16,
                        acc[i][j], LDC_, wmma::mem_row_major);
        }
        __syncthreads();
        #pragma unroll
        for (int e = 0; e < 16; e++) {
            int lin = e * 256 + tid;
            int row = lin >> 5;
            int c4  = lin & 31;
            int m   = m0 + p * 128 + row;            // global row (b*T + t)
            size_t grow;
            if (comp) {
                int pp = posmap[m];
                if (pp < 0) continue;                 // masked key: no write
                int bb = m >> 11;                     // T_ = 2048
                grow = ((size_t)(bb * T_ + pp)) * C_ + n0 + c4 * 4;
            } else {
                grow = (size_t)m * C_ + n0 + c4 * 4;
            }
            float4 v = *(const float4*)(St + row * LDC_ + c4 * 4);
            v.x += bias[n0 + c4 * 4 + 0];
            v.y += bias[n0 + c4 * 4 + 1];
            v.z += bias[n0 + c4 * 4 + 2];
            v.w += bias[n0 + c4 * 4 + 3];
            if (CF) {
                *(float4*)(CF + grow) = v;
            } else {
                *(__half2*)(Cm + grow + 0) = __floats2half2_rn(v.x, v.y);
                *(__half2*)(Cm + grow + 2) = __floats2half2_rn(v.z, v.w);
            }
        }
        __syncthreads();
    }
}

// ===========================================================================
// mma.sync attention over CONTIGUOUS compacted K/V (no gather indirection).
// 64 q-rows per CTA, 4 warps, S/P/O register-resident. Tail mask positional.
// ===========================================================================
#define KLD 72

#define AOF_K0 0
#define AOF_K1 (64*KLD*2)
#define AOF_V0 (2*64*KLD*2)
#define AOF_V1 (3*64*KLD*2)
#define AOF_Q  (4*64*KLD*2)
#define ATTN_SMEM (AOF_Q + 64*KLD*2)     // 46080

__global__ __launch_bounds__(128) void attn_m()
{
    extern __shared__ char smc[];
    const uint32_t sb = smem_u32(smc);

    const int tid  = threadIdx.x;
    const int w    = tid >> 5;
    const int lane = tid & 31;
    const int q4   = lane & 3;
    const int lrow = lane & 15;
    const int lc8  = (lane >> 4) * 8;

    const int t0 = blockIdx.x * 64;
    const int h  = blockIdx.y;
    const int b  = blockIdx.z;

    const __half* Qg = g_hq + (size_t)b * T_ * C_ + h * HD_;
    const __half* Kg = g_hk + (size_t)b * T_ * C_ + h * HD_;   // compacted rows
    const __half* Vg = g_hv + (size_t)b * T_ * C_ + h * HD_;   // compacted rows

    const int nv = g_nvalid[b];
    const int ntiles = (nv + 63) >> 6;

    auto stageKV = [&](int buf, int kt) {
        int k0 = kt * 64;
        uint32_t Kd = sb + (buf ? AOF_K1 : AOF_K0);
        uint32_t Vd = sb + (buf ? AOF_V1 : AOF_V0);
        #pragma unroll
        for (int e = 0; e < 4; e++) {
            int lin = e * 128 + tid;
            int row = lin >> 3, c8 = lin & 7;
            int gi  = k0 + row;
            int src = (gi < nv) ? gi : 0;           // pure-ALU clamp, no LDG
            uint32_t off = (uint32_t)(row * KLD + c8 * 8) * 2;
            cp16(Kd + off, Kg + (size_t)src * C_ + c8 * 8);
            cp16(Vd + off, Vg + (size_t)src * C_ + c8 * 8);
        }
    };

    #pragma unroll
    for (int e = 0; e < 4; e++) {
        int lin = e * 128 + tid;
        int row = lin >> 3, c8 = lin & 7;
        cp16(sb + AOF_Q + (uint32_t)(row * KLD + c8 * 8) * 2,
             Qg + (size_t)(t0 + row) * C_ + c8 * 8);
    }
    stageKV(0, 0);
    CP_COMMIT();
    CP_WAIT(0);
    __syncthreads();

    uint32_t qa[4][4];
    #pragma unroll
    for (int c = 0; c < 4; c++)
        ldm4(qa[c], sb + AOF_Q + (uint32_t)((w * 16 + lrow) * KLD + c * 16 + lc8) * 2);

    float oacc[8][4];
    #pragma unroll
    for (int nb = 0; nb < 8; nb++)
        #pragma unroll
        for (int e = 0; e < 4; e++)
            oacc[nb][e] = 0.0f;

    float lsum0 = 0.0f, lsum1 = 0.0f;

    for (int kt = 0; kt < ntiles; kt++) {
        const int bb = kt & 1;
        if (kt + 1 < ntiles) { stageKV(bb ^ 1, kt + 1); CP_COMMIT(); }

        float sacc[8][4];
        #pragma unroll
        for (int nb = 0; nb < 8; nb++)
            #pragma unroll
            for (int e = 0; e < 4; e++)
                sacc[nb][e] = 0.0f;

        uint32_t kbase = sb + (bb ? AOF_K1 : AOF_K0);
        #pragma unroll
        for (int c = 0; c < 4; c++) {
            #pragma unroll
            for (int j = 0; j < 4; j++) {
                uint32_t kr[4];
                ldm4(kr, kbase + (uint32_t)((16 * j + lrow) * KLD + c * 16 + lc8) * 2);
                uint32_t bA[2] = { kr[0], kr[2] };
                uint32_t bB[2] = { kr[1], kr[3] };
                mma_f16(sacc[2 * j + 0], qa[c], bA);
                mma_f16(sacc[2 * j + 1], qa[c], bB);
            }
        }

        const int k0 = kt * 64;
        uint32_t pa[4][4];
        #pragma unroll
        for (int j = 0; j < 4; j++) {
            #pragma unroll
            for (int sub = 0; sub < 2; sub++) {
                int nb = 2 * j + sub;
                int col = k0 + nb * 8 + 2 * q4;
                float m0 = (col     < nv) ? 0.0f : -1e30f;
                float m1 = (col + 1 < nv) ? 0.0f : -1e30f;
                float p0 = __expf(fmaf(sacc[nb][0], 0.125f, m0));
                float p1 = __expf(fmaf(sacc[nb][1], 0.125f, m1));
                float p2 = __expf(fmaf(sacc[nb][2], 0.125f, m0));
                float p3 = __expf(fmaf(sacc[nb][3], 0.125f, m1));
                lsum0 += p0 + p1;
                lsum1 += p2 + p3;
                pa[j][2 * sub + 0] = pack_h2(p0, p1);
                pa[j][2 * sub + 1] = pack_h2(p2, p3);
            }
        }

        uint32_t vbase = sb + (bb ? AOF_V1 : AOF_V0);
        #pragma unroll
        for (int j = 0; j < 4; j++) {
            #pragma unroll
            for (int np = 0; np < 4; np++) {
                uint32_t vr[4];
                ldm4t(vr, vbase + (uint32_t)((16 * j + lrow) * KLD + np * 16 + lc8) * 2);
                uint32_t bA[2] = { vr[0], vr[1] };
                uint32_t bB[2] = { vr[2], vr[3] };
                mma_f16(oacc[2 * np + 0], pa[j], bA);
                mma_f16(oacc[2 * np + 1], pa[j], bB);
            }
        }

        if (kt + 1 < ntiles) CP_WAIT(0);
        __syncthreads();
    }

    lsum0 += __shfl_xor_sync(0xffffffffu, lsum0, 1);
    lsum0 += __shfl_xor_sync(0xffffffffu, lsum0, 2);
    lsum1 += __shfl_xor_sync(0xffffffffu, lsum1, 1);
    lsum1 += __shfl_xor_sync(0xffffffffu, lsum1, 2);
    float r0 = 1.0f / lsum0;
    float r1 = 1.0f / lsum1;

    __half* Yb = g_hy + (size_t)b * T_ * C_ + h * HD_;
    const int row0 = t0 + w * 16 + (lane >> 2);
    #pragma unroll
    for (int nb = 0; nb < 8; nb++) {
        int col = nb * 8 + 2 * q4;
        *(__half2*)(Yb + (size_t)row0 * C_ + col) =
            __floats2half2_rn(oacc[nb][0] * r0, oacc[nb][1] * r0);
        *(__half2*)(Yb + (size_t)(row0 + 8) * C_ + col) =
            __floats2half2_rn(oacc[nb][2] * r1, oacc[nb][3] * r1);
    }
}

// ---------------------------------------------------------------------------
extern "C" void kernel_launch(void* const* d_in, const int* in_sizes, int n_in,
                              void* d_out, int out_size)
{
    const float* x    = (const float*)d_in[0];
    const int*   mask = (const int*)  d_in[1];
    const float* Wq   = (const float*)d_in[2];
    const float* bq   = (const float*)d_in[3];
    const float* Wk   = (const float*)d_in[4];
    const float* bk   = (const float*)d_in[5];
    const float* Wv   = (const float*)d_in[6];
    const float* bv   = (const float*)d_in[7];
    const float* Wp   = (const float*)d_in[8];
    const float* bp   = (const float*)d_in[9];
    float* out = (float*)d_out;

    __half *hx, *hq, *hk, *hv, *hy, *hwq, *hwk, *hwv, *hwp;
    int *pmap;
    cudaGetSymbolAddress((void**)&hx,  g_hx);
    cudaGetSymbolAddress((void**)&hq,  g_hq);
    cudaGetSymbolAddress((void**)&hk,  g_hk);
    cudaGetSymbolAddress((void**)&hv,  g_hv);
    cudaGetSymbolAddress((void**)&hy,  g_hy);
    cudaGetSymbolAddress((void**)&hwq, g_hwq);
    cudaGetSymbolAddress((void**)&hwk, g_hwk);
    cudaGetSymbolAddress((void**)&hwv, g_hwv);
    cudaGetSymbolAddress((void**)&hwp, g_hwp);
    cudaGetSymbolAddress((void**)&pmap, g_pos);

    cudaFuncSetAttribute(gemm_h, cudaFuncAttributeMaxDynamicSharedMemorySize, SMEM_GEMM_);
    cudaFuncSetAttribute(attn_m, cudaFuncAttributeMaxDynamicSharedMemorySize, ATTN_SMEM);
    cudaFuncSetAttribute(attn_m, cudaFuncAttributePreferredSharedMemoryCarveout, 100);

    f2h5<<<(N4TOT_ + 255) / 256, 256>>>(x, Wq, Wk, Wv, Wp);
    scan_mask<<<B_, 128>>>(mask);

    // fused Q/K/V projections; K/V rows scattered to compact positions
    gemm_h<<<dim3(M_ / 256, 18), 256, SMEM_GEMM_>>>(
        hx, hwq, hwk, hwv, bq, bk, bv, hq, hk, hv, nullptr, pmap);

    attn_m<<<dim3(T_ / 64, H_, B_), 128, ATTN_SMEM>>>();

    // output projection (fp32 out, no compaction)
    gemm_h<<<dim3(M_ / 256, 6), 256, SMEM_GEMM_>>>(
        hy, hwp, hwp, hwp, bp, bp, bp, nullptr, nullptr, nullptr, out, nullptr);
}

// round 16
// speedup vs baseline: 1.0776x; 1.0776x over previous
#include <cuda_runtime.h>
#include <cuda_fp16.h>
#include <mma.h>
#include <cstdint>
#include <math.h>

using namespace nvcuda;

#define B_  2
#define T_  2048
#define C_  768
#define H_  12
#define HD_ 64
#define M_  (B_*T_)   // 4096

// Scratch (allocations forbidden -> device globals)
__device__ __half g_hx[M_*C_];
__device__ __half g_hxc[M_*C_];  // COMPACTED x rows (per batch, rows [0,nvalid))
__device__ __half g_hq[M_*C_];
__device__ __half g_hk[M_*C_];   // compact K (computed from compacted x)
__device__ __half g_hv[M_*C_];   // compact V
__device__ __half g_hy[M_*C_];
__device__ __half g_hwq[C_*C_];
__device__ __half g_hwk[C_*C_];
__device__ __half g_hwv[C_*C_];
__device__ __half g_hwp[C_*C_];
__device__ int    g_cidx[M_];    // compacted valid-key indices per batch
__device__ int    g_nvalid[B_];  // valid-key count per batch

// ---------------------------------------------------------------------------
__device__ __forceinline__ uint32_t smem_u32(const void* p) {
    uint32_t r;
    asm("{ .reg .u64 t; cvta.to.shared.u64 t, %1; cvt.u32.u64 %0, t; }"
        : "=r"(r) : "l"(p));
    return r;
}
__device__ __forceinline__ void cp16(uint32_t dst, const void* src) {
    asm volatile("cp.async.ca.shared.global [%0], [%1], 16;" :: "r"(dst), "l"(src));
}
#define CP_COMMIT() asm volatile("cp.async.commit_group;" ::: "memory")
#define CP_WAIT(N)  asm volatile("cp.async.wait_group %0;" :: "n"(N) : "memory")

__device__ __forceinline__ void ldm4(uint32_t r[4], uint32_t a) {
    asm volatile("ldmatrix.sync.aligned.m8n8.x4.shared.b16 {%0,%1,%2,%3}, [%4];"
        : "=r"(r[0]), "=r"(r[1]), "=r"(r[2]), "=r"(r[3]) : "r"(a));
}
__device__ __forceinline__ void ldm4t(uint32_t r[4], uint32_t a) {
    asm volatile("ldmatrix.sync.aligned.m8n8.x4.trans.shared.b16 {%0,%1,%2,%3}, [%4];"
        : "=r"(r[0]), "=r"(r[1]), "=r"(r[2]), "=r"(r[3]) : "r"(a));
}
__device__ __forceinline__ void mma_f16(float d[4], const uint32_t a[4], const uint32_t b[2]) {
    asm volatile(
        "mma.sync.aligned.m16n8k16.row.col.f32.f16.f16.f32 "
        "{%0,%1,%2,%3}, {%4,%5,%6,%7}, {%8,%9}, {%0,%1,%2,%3};"
        : "+f"(d[0]), "+f"(d[1]), "+f"(d[2]), "+f"(d[3])
        : "r"(a[0]), "r"(a[1]), "r"(a[2]), "r"(a[3]), "r"(b[0]), "r"(b[1]));
}
__device__ __forceinline__ uint32_t pack_h2(float p0, float p1) {
    uint32_t u;
    asm("cvt.rn.f16x2.f32 %0, %1, %2;" : "=r"(u) : "f"(p1), "f"(p0));
    return u;
}

// ---------------------------------------------------------------------------
// fused f32 -> f16 convert: x + 4 weight matrices in ONE launch
// ---------------------------------------------------------------------------
#define X4_ (M_*C_/4)
#define W4_ (C_*C_/4)
#define N4TOT_ (X4_ + 4*W4_)

__global__ void f2h5(const float* __restrict__ x,
                     const float* __restrict__ w0, const float* __restrict__ w1,
                     const float* __restrict__ w2, const float* __restrict__ w3)
{
    int i = blockIdx.x * blockDim.x + threadIdx.x;
    if (i >= N4TOT_) return;
    const float* s;
    __half* d;
    int k;
    if (i < X4_) { s = x; d = g_hx; k = i; }
    else {
        int j = i - X4_;
        int seg = j / W4_;
        k = j - seg * W4_;
        s = (seg == 0) ? w0 : (seg == 1) ? w1 : (seg == 2) ? w2 : w3;
        d = (seg == 0) ? g_hwq : (seg == 1) ? g_hwk : (seg == 2) ? g_hwv : g_hwp;
    }
    float4 v = ((const float4*)s)[k];
    ((__half2*)d)[2 * k + 0] = __floats2half2_rn(v.x, v.y);
    ((__half2*)d)[2 * k + 1] = __floats2half2_rn(v.z, v.w);
}

// ---------------------------------------------------------------------------
// Deterministic mask scan: cidx (ascending valid key indices) + nvalid.
// ---------------------------------------------------------------------------
__global__ void scan_mask(const int* __restrict__ mask)
{
    int b = blockIdx.x;
    int t = threadIdx.x;            // 0..127
    int lane = t & 31, wid = t >> 5;
    const int* mb = mask + b * T_;

    int base = t * 16;
    int v[16];
    int loc = 0;
    #pragma unroll
    for (int j = 0; j < 16; j++) { v[j] = (mb[base + j] != 0); loc += v[j]; }

    int x = loc;
    #pragma unroll
    for (int off = 1; off < 32; off <<= 1) {
        int y = __shfl_up_sync(0xffffffffu, x, off);
        if (lane >= off) x += y;
    }
    __shared__ int wsum[4];
    if (lane == 31) wsum[wid] = x;
    __syncthreads();
    int woff = 0;
    #pragma unroll
    for (int i = 0; i < 4; i++) if (i < wid) woff += wsum[i];
    int pos = woff + x - loc;

    #pragma unroll
    for (int j = 0; j < 16; j++)
        if (v[j]) g_cidx[b * T_ + pos++] = base + j;

    if (t == 0) g_nvalid[b] = wsum[0] + wsum[1] + wsum[2] + wsum[3];
}

// ---------------------------------------------------------------------------
// gather compacted x rows (half): one block per compact row.
// 192 threads x 4 halfs = 768. Rows >= nvalid left untouched (zeros, unused).
// ---------------------------------------------------------------------------
__global__ void gather_x()
{
    int i = blockIdx.x;             // compact row within batch
    int b = blockIdx.y;
    if (i >= g_nvalid[b]) return;
    int src = g_cidx[b * T_ + i];
    const uint64_t* sp = (const uint64_t*)(g_hx  + ((size_t)b * T_ + src) * C_);
    uint64_t*       dp = (uint64_t*)      (g_hxc + ((size_t)b * T_ + i)   * C_);
    dp[threadIdx.x] = sp[threadIdx.x];   // 8 bytes = 4 halfs per thread
}

// ===========================================================================
// fp16 WMMA GEMM (R8 mainloop): CTA 256x128, BK=64, 8 warps, warp tile 64x64.
// which==0 uses A0 (full M); which 1/2 use A1 (compacted x) and early-exit
// m-tiles entirely above nvalid[batch]. Tile 256 divides T_ -> no straddle.
// ===========================================================================
#define LDH  72
#define LDC_ 132
#define NCH  12

#define G_A_SZ (256*LDH*2)
#define G_W_SZ (128*LDH*2)
#define G_BUF  (G_A_SZ + G_W_SZ)
#define SMEM_GEMM_ (2*G_BUF)

__global__ __launch_bounds__(256) void gemm_h(
    const __half* __restrict__ A0, const __half* __restrict__ A1,
    const __half* __restrict__ W0, const __half* __restrict__ W1, const __half* __restrict__ W2,
    const float* __restrict__ b0, const float* __restrict__ b1, const float* __restrict__ b2,
    __half* __restrict__ C0, __half* __restrict__ C1, __half* __restrict__ C2,
    float* __restrict__ CF)
{
    extern __shared__ char smc[];
    float* St = (float*)smc;
    const uint32_t sb = smem_u32(smc);

    const int tid = threadIdx.x;
    const int wid = tid >> 5;
    const int warp_m = wid & 3;
    const int warp_n = wid >> 2;

    const int m0 = blockIdx.x * 256;
    const int which = blockIdx.y / 6;
    const int n0 = (blockIdx.y % 6) * 128;

    // K/V matrices: skip m-tiles entirely beyond this batch's valid-key count
    if (which != 0) {
        int bb = m0 >> 11;                       // T_ = 2048
        if ((m0 & 2047) >= g_nvalid[bb]) return;
    }

    const __half* A   = (which == 0) ? A0 : A1;
    const __half* W   = (which == 0) ? W0 : (which == 1) ? W1 : W2;
    const float* bias = (which == 0) ? b0 : (which == 1) ? b1 : b2;
    __half*      Cm   = (which == 0) ? C0 : (which == 1) ? C1 : C2;

    const __half* Arow = A + (size_t)m0 * C_;
    const __half* Wrow = W + (size_t)n0 * C_;

    wmma::fragment<wmma::accumulator, 16, 16, 16, float> acc[4][4];
    #pragma unroll
    for (int i = 0; i < 4; i++)
        #pragma unroll
        for (int j = 0; j < 4; j++)
            wmma::fill_fragment(acc[i][j], 0.0f);

    auto stage = [&](int buf, int k0) {
        uint32_t Ad = sb + (buf ? (uint32_t)G_BUF : 0u);
        uint32_t Wd = Ad + (uint32_t)G_A_SZ;
        #pragma unroll
        for (int e = 0; e < 8; e++) {
            int lin = e * 256 + tid;
            int row = lin >> 3, c8 = lin & 7;
            cp16(Ad + (uint32_t)(row * LDH + c8 * 8) * 2,
                 Arow + (size_t)row * C_ + k0 + c8 * 8);
        }
        #pragma unroll
        for (int e = 0; e < 4; e++) {
            int lin = e * 256 + tid;
            int row = lin >> 3, c8 = lin & 7;
            cp16(Wd + (uint32_t)(row * LDH + c8 * 8) * 2,
                 Wrow + (size_t)row * C_ + k0 + c8 * 8);
        }
    };

    stage(0, 0);
    CP_COMMIT();

    for (int c = 0; c < NCH; c++) {
        const int b = c & 1;
        if (c < NCH - 1) { stage(b ^ 1, (c + 1) * 64); CP_COMMIT(); CP_WAIT(1); }
        else             { CP_WAIT(0); }
        __syncthreads();

        const __half* Ab = (const __half*)(smc + (b ? G_BUF : 0));
        const __half* Wb = (const __half*)((const char*)Ab + G_A_SZ);
        #pragma unroll
        for (int ks = 0; ks < 4; ks++) {
            wmma::fragment<wmma::matrix_a, 16, 16, 16, __half, wmma::row_major> af[4];
            #pragma unroll
            for (int i = 0; i < 4; i++)
                wmma::load_matrix_sync(af[i], Ab + (warp_m * 64 + i * 16) * LDH + ks * 16, LDH);
            #pragma unroll
            for (int j = 0; j < 4; j++) {
                wmma::fragment<wmma::matrix_b, 16, 16, 16, __half, wmma::col_major> bf;
                wmma::load_matrix_sync(bf, Wb + (warp_n * 64 + j * 16) * LDH + ks * 16, LDH);
                #pragma unroll
                for (int i = 0; i < 4; i++)
                    wmma::mma_sync(acc[i][j], af[i], bf, acc[i][j]);
            }
        }
        __syncthreads();
    }

    #pragma unroll
    for (int p = 0; p < 2; p++) {
        if ((warp_m >> 1) == p) {
            int lm = (warp_m & 1) * 64;
            #pragma unroll
            for (int i = 0; i < 4; i++)
                #pragma unroll
                for (int j = 0; j < 4; j++)
                    wmma::store_matrix_sync(
                        St + (lm + i * 16) * LDC_ + warp_n * 64 + j * 16,
                        acc[i][j], LDC_, wmma::mem_row_major);
        }
        __syncthreads();
        #pragma unroll
        for (int e = 0; e < 16; e++) {
            int lin = e * 256 + tid;
            int row = lin >> 5;
            int c4  = lin & 31;
            float4 v = *(const float4*)(St + row * LDC_ + c4 * 4);
            v.x += bias[n0 + c4 * 4 + 0];
            v.y += bias[n0 + c4 * 4 + 1];
            v.z += bias[n0 + c4 * 4 + 2];
            v.w += bias[n0 + c4 * 4 + 3];
            size_t grow = (size_t)(m0 + p * 128 + row) * C_ + n0 + c4 * 4;
            if (CF) {
                *(float4*)(CF + grow) = v;
            } else {
                *(__half2*)(Cm + grow + 0) = __floats2half2_rn(v.x, v.y);
                *(__half2*)(Cm + grow + 2) = __floats2half2_rn(v.z, v.w);
            }
        }
        __syncthreads();
    }
}

// ===========================================================================
// mma.sync attention over CONTIGUOUS compact K/V (R15 attn — no gather).
// 64 q-rows per CTA, 4 warps, S/P/O register-resident. Tail mask positional.
// ===========================================================================
#define KLD 72

#define AOF_K0 0
#define AOF_K1 (64*KLD*2)
#define AOF_V0 (2*64*KLD*2)
#define AOF_V1 (3*64*KLD*2)
#define AOF_Q  (4*64*KLD*2)
#define ATTN_SMEM (AOF_Q + 64*KLD*2)     // 46080

__global__ __launch_bounds__(128) void attn_m()
{
    extern __shared__ char smc[];
    const uint32_t sb = smem_u32(smc);

    const int tid  = threadIdx.x;
    const int w    = tid >> 5;
    const int lane = tid & 31;
    const int q4   = lane & 3;
    const int lrow = lane & 15;
    const int lc8  = (lane >> 4) * 8;

    const int t0 = blockIdx.x * 64;
    const int h  = blockIdx.y;
    const int b  = blockIdx.z;

    const __half* Qg = g_hq + (size_t)b * T_ * C_ + h * HD_;
    const __half* Kg = g_hk + (size_t)b * T_ * C_ + h * HD_;   // compact rows
    const __half* Vg = g_hv + (size_t)b * T_ * C_ + h * HD_;   // compact rows

    const int nv = g_nvalid[b];
    const int ntiles = (nv + 63) >> 6;

    auto stageKV = [&](int buf, int kt) {
        int k0 = kt * 64;
        uint32_t Kd = sb + (buf ? AOF_K1 : AOF_K0);
        uint32_t Vd = sb + (buf ? AOF_V1 : AOF_V0);
        #pragma unroll
        for (int e = 0; e < 4; e++) {
            int lin = e * 128 + tid;
            int row = lin >> 3, c8 = lin & 7;
            int gi  = k0 + row;
            int src = (gi < nv) ? gi : 0;           // pure-ALU clamp, no LDG
            uint32_t off = (uint32_t)(row * KLD + c8 * 8) * 2;
            cp16(Kd + off, Kg + (size_t)src * C_ + c8 * 8);
            cp16(Vd + off, Vg + (size_t)src * C_ + c8 * 8);
        }
    };

    #pragma unroll
    for (int e = 0; e < 4; e++) {
        int lin = e * 128 + tid;
        int row = lin >> 3, c8 = lin & 7;
        cp16(sb + AOF_Q + (uint32_t)(row * KLD + c8 * 8) * 2,
             Qg + (size_t)(t0 + row) * C_ + c8 * 8);
    }
    stageKV(0, 0);
    CP_COMMIT();
    CP_WAIT(0);
    __syncthreads();

    uint32_t qa[4][4];
    #pragma unroll
    for (int c = 0; c < 4; c++)
        ldm4(qa[c], sb + AOF_Q + (uint32_t)((w * 16 + lrow) * KLD + c * 16 + lc8) * 2);

    float oacc[8][4];
    #pragma unroll
    for (int nb = 0; nb < 8; nb++)
        #pragma unroll
        for (int e = 0; e < 4; e++)
            oacc[nb][e] = 0.0f;

    float lsum0 = 0.0f, lsum1 = 0.0f;

    for (int kt = 0; kt < ntiles; kt++) {
        const int bb = kt & 1;
        if (kt + 1 < ntiles) { stageKV(bb ^ 1, kt + 1); CP_COMMIT(); }

        float sacc[8][4];
        #pragma unroll
        for (int nb = 0; nb < 8; nb++)
            #pragma unroll
            for (int e = 0; e < 4; e++)
                sacc[nb][e] = 0.0f;

        uint32_t kbase = sb + (bb ? AOF_K1 : AOF_K0);
        #pragma unroll
        for (int c = 0; c < 4; c++) {
            #pragma unroll
            for (int j = 0; j < 4; j++) {
                uint32_t kr[4];
                ldm4(kr, kbase + (uint32_t)((16 * j + lrow) * KLD + c * 16 + lc8) * 2);
                uint32_t bA[2] = { kr[0], kr[2] };
                uint32_t bB[2] = { kr[1], kr[3] };
                mma_f16(sacc[2 * j + 0], qa[c], bA);
                mma_f16(sacc[2 * j + 1], qa[c], bB);
            }
        }

        const int k0 = kt * 64;
        uint32_t pa[4][4];
        #pragma unroll
        for (int j = 0; j < 4; j++) {
            #pragma unroll
            for (int sub = 0; sub < 2; sub++) {
                int nb = 2 * j + sub;
                int col = k0 + nb * 8 + 2 * q4;
                float m0 = (col     < nv) ? 0.0f : -1e30f;
                float m1 = (col + 1 < nv) ? 0.0f : -1e30f;
                float p0 = __expf(fmaf(sacc[nb][0], 0.125f, m0));
                float p1 = __expf(fmaf(sacc[nb][1], 0.125f, m1));
                float p2 = __expf(fmaf(sacc[nb][2], 0.125f, m0));
                float p3 = __expf(fmaf(sacc[nb][3], 0.125f, m1));
                lsum0 += p0 + p1;
                lsum1 += p2 + p3;
                pa[j][2 * sub + 0] = pack_h2(p0, p1);
                pa[j][2 * sub + 1] = pack_h2(p2, p3);
            }
        }

        uint32_t vbase = sb + (bb ? AOF_V1 : AOF_V0);
        #pragma unroll
        for (int j = 0; j < 4; j++) {
            #pragma unroll
            for (int np = 0; np < 4; np++) {
                uint32_t vr[4];
                ldm4t(vr, vbase + (uint32_t)((16 * j + lrow) * KLD + np * 16 + lc8) * 2);
                uint32_t bA[2] = { vr[0], vr[1] };
                uint32_t bB[2] = { vr[2], vr[3] };
                mma_f16(oacc[2 * np + 0], pa[j], bA);
                mma_f16(oacc[2 * np + 1], pa[j], bB);
            }
        }

        if (kt + 1 < ntiles) CP_WAIT(0);
        __syncthreads();
    }

    lsum0 += __shfl_xor_sync(0xffffffffu, lsum0, 1);
    lsum0 += __shfl_xor_sync(0xffffffffu, lsum0, 2);
    lsum1 += __shfl_xor_sync(0xffffffffu, lsum1, 1);
    lsum1 += __shfl_xor_sync(0xffffffffu, lsum1, 2);
    float r0 = 1.0f / lsum0;
    float r1 = 1.0f / lsum1;

    __half* Yb = g_hy + (size_t)b * T_ * C_ + h * HD_;
    const int row0 = t0 + w * 16 + (lane >> 2);
    #pragma unroll
    for (int nb = 0; nb < 8; nb++) {
        int col = nb * 8 + 2 * q4;
        *(__half2*)(Yb + (size_t)row0 * C_ + col) =
            __floats2half2_rn(oacc[nb][0] * r0, oacc[nb][1] * r0);
        *(__half2*)(Yb + (size_t)(row0 + 8) * C_ + col) =
            __floats2half2_rn(oacc[nb][2] * r1, oacc[nb][3] * r1);
    }
}

// ---------------------------------------------------------------------------
extern "C" void kernel_launch(void* const* d_in, const int* in_sizes, int n_in,
                              void* d_out, int out_size)
{
    const float* x    = (const float*)d_in[0];
    const int*   mask = (const int*)  d_in[1];
    const float* Wq   = (const float*)d_in[2];
    const float* bq   = (const float*)d_in[3];
    const float* Wk   = (const float*)d_in[4];
    const float* bk   = (const float*)d_in[5];
    const float* Wv   = (const float*)d_in[6];
    const float* bv   = (const float*)d_in[7];
    const float* Wp   = (const float*)d_in[8];
    const float* bp   = (const float*)d_in[9];
    float* out = (float*)d_out;

    __half *hx, *hxc, *hq, *hk, *hv, *hy, *hwq, *hwk, *hwv, *hwp;
    cudaGetSymbolAddress((void**)&hx,  g_hx);
    cudaGetSymbolAddress((void**)&hxc, g_hxc);
    cudaGetSymbolAddress((void**)&hq,  g_hq);
    cudaGetSymbolAddress((void**)&hk,  g_hk);
    cudaGetSymbolAddress((void**)&hv,  g_hv);
    cudaGetSymbolAddress((void**)&hy,  g_hy);
    cudaGetSymbolAddress((void**)&hwq, g_hwq);
    cudaGetSymbolAddress((void**)&hwk, g_hwk);
    cudaGetSymbolAddress((void**)&hwv, g_hwv);
    cudaGetSymbolAddress((void**)&hwp, g_hwp);

    cudaFuncSetAttribute(gemm_h, cudaFuncAttributeMaxDynamicSharedMemorySize, SMEM_GEMM_);
    cudaFuncSetAttribute(attn_m, cudaFuncAttributeMaxDynamicSharedMemorySize, ATTN_SMEM);
    cudaFuncSetAttribute(attn_m, cudaFuncAttributePreferredSharedMemoryCarveout, 100);

    f2h5<<<(N4TOT_ + 255) / 256, 256>>>(x, Wq, Wk, Wv, Wp);
    scan_mask<<<B_, 128>>>(mask);
    gather_x<<<dim3(T_, B_), 192>>>();

    // Q from full hx; K/V from compacted hxc (early-exit tiles beyond nvalid)
    gemm_h<<<dim3(M_ / 256, 18), 256, SMEM_GEMM_>>>(
        hx, hxc, hwq, hwk, hwv, bq, bk, bv, hq, hk, hv, nullptr);

    attn_m<<<dim3(T_ / 64, H_, B_), 128, ATTN_SMEM>>>();

    // output projection (fp32 out, full M)
    gemm_h<<<dim3(M_ / 256, 6), 256, SMEM_GEMM_>>>(
        hy, hy, hwp, hwp, hwp, bp, bp, bp, nullptr, nullptr, nullptr, out);
}

// round 17
// speedup vs baseline: 1.0937x; 1.0149x over previous
#include <cuda_runtime.h>
#include <cuda_fp16.h>
#include <mma.h>
#include <cstdint>
#include <math.h>

using namespace nvcuda;

#define B_  2
#define T_  2048
#define C_  768
#define H_  12
#define HD_ 64
#define M_  (B_*T_)   // 4096

// Scratch (allocations forbidden -> device globals)
__device__ __half g_hx[M_*C_];
__device__ __half g_hxc[M_*C_];  // COMPACTED x rows (per batch, rows [0,nvalid))
__device__ __half g_hq[M_*C_];
__device__ __half g_hk[M_*C_];   // compact K (computed from compacted x)
__device__ __half g_hv[M_*C_];   // compact V
__device__ __half g_hy[M_*C_];
__device__ __half g_hwq[C_*C_];
__device__ __half g_hwk[C_*C_];
__device__ __half g_hwv[C_*C_];
__device__ __half g_hwp[C_*C_];
__device__ int    g_cidx[M_];    // compacted valid-key indices per batch
__device__ int    g_nvalid[B_];  // valid-key count per batch

// ---------------------------------------------------------------------------
__device__ __forceinline__ uint32_t smem_u32(const void* p) {
    uint32_t r;
    asm("{ .reg .u64 t; cvta.to.shared.u64 t, %1; cvt.u32.u64 %0, t; }"
        : "=r"(r) : "l"(p));
    return r;
}
__device__ __forceinline__ void cp16(uint32_t dst, const void* src) {
    asm volatile("cp.async.ca.shared.global [%0], [%1], 16;" :: "r"(dst), "l"(src));
}
#define CP_COMMIT() asm volatile("cp.async.commit_group;" ::: "memory")
#define CP_WAIT(N)  asm volatile("cp.async.wait_group %0;" :: "n"(N) : "memory")

__device__ __forceinline__ void ldm4(uint32_t r[4], uint32_t a) {
    asm volatile("ldmatrix.sync.aligned.m8n8.x4.shared.b16 {%0,%1,%2,%3}, [%4];"
        : "=r"(r[0]), "=r"(r[1]), "=r"(r[2]), "=r"(r[3]) : "r"(a));
}
__device__ __forceinline__ void ldm4t(uint32_t r[4], uint32_t a) {
    asm volatile("ldmatrix.sync.aligned.m8n8.x4.trans.shared.b16 {%0,%1,%2,%3}, [%4];"
        : "=r"(r[0]), "=r"(r[1]), "=r"(r[2]), "=r"(r[3]) : "r"(a));
}
__device__ __forceinline__ void mma_f16(float d[4], const uint32_t a[4], const uint32_t b[2]) {
    asm volatile(
        "mma.sync.aligned.m16n8k16.row.col.f32.f16.f16.f32 "
        "{%0,%1,%2,%3}, {%4,%5,%6,%7}, {%8,%9}, {%0,%1,%2,%3};"
        : "+f"(d[0]), "+f"(d[1]), "+f"(d[2]), "+f"(d[3])
        : "r"(a[0]), "r"(a[1]), "r"(a[2]), "r"(a[3]), "r"(b[0]), "r"(b[1]));
}
__device__ __forceinline__ uint32_t pack_h2(float p0, float p1) {
    uint32_t u;
    asm("cvt.rn.f16x2.f32 %0, %1, %2;" : "=r"(u) : "f"(p1), "f"(p0));
    return u;
}

// ---------------------------------------------------------------------------
// fused f32 -> f16 convert: x + 4 weight matrices in ONE launch
// ---------------------------------------------------------------------------
#define X4_ (M_*C_/4)
#define W4_ (C_*C_/4)
#define N4TOT_ (X4_ + 4*W4_)

__global__ void f2h5(const float* __restrict__ x,
                     const float* __restrict__ w0, const float* __restrict__ w1,
                     const float* __restrict__ w2, const float* __restrict__ w3)
{
    int i = blockIdx.x * blockDim.x + threadIdx.x;
    if (i >= N4TOT_) return;
    const float* s;
    __half* d;
    int k;
    if (i < X4_) { s = x; d = g_hx; k = i; }
    else {
        int j = i - X4_;
        int seg = j / W4_;
        k = j - seg * W4_;
        s = (seg == 0) ? w0 : (seg == 1) ? w1 : (seg == 2) ? w2 : w3;
        d = (seg == 0) ? g_hwq : (seg == 1) ? g_hwk : (seg == 2) ? g_hwv : g_hwp;
    }
    float4 v = ((const float4*)s)[k];
    ((__half2*)d)[2 * k + 0] = __floats2half2_rn(v.x, v.y);
    ((__half2*)d)[2 * k + 1] = __floats2half2_rn(v.z, v.w);
}

// ---------------------------------------------------------------------------
// Deterministic mask scan: cidx (ascending valid key indices) + nvalid.
// ---------------------------------------------------------------------------
__global__ void scan_mask(const int* __restrict__ mask)
{
    int b = blockIdx.x;
    int t = threadIdx.x;            // 0..127
    int lane = t & 31, wid = t >> 5;
    const int* mb = mask + b * T_;

    int base = t * 16;
    int v[16];
    int loc = 0;
    #pragma unroll
    for (int j = 0; j < 16; j++) { v[j] = (mb[base + j] != 0); loc += v[j]; }

    int x = loc;
    #pragma unroll
    for (int off = 1; off < 32; off <<= 1) {
        int y = __shfl_up_sync(0xffffffffu, x, off);
        if (lane >= off) x += y;
    }
    __shared__ int wsum[4];
    if (lane == 31) wsum[wid] = x;
    __syncthreads();
    int woff = 0;
    #pragma unroll
    for (int i = 0; i < 4; i++) if (i < wid) woff += wsum[i];
    int pos = woff + x - loc;

    #pragma unroll
    for (int j = 0; j < 16; j++)
        if (v[j]) g_cidx[b * T_ + pos++] = base + j;

    if (t == 0) g_nvalid[b] = wsum[0] + wsum[1] + wsum[2] + wsum[3];
}

// ---------------------------------------------------------------------------
// gather compacted x rows (half): one block per compact row.
// ---------------------------------------------------------------------------
__global__ void gather_x()
{
    int i = blockIdx.x;             // compact row within batch
    int b = blockIdx.y;
    if (i >= g_nvalid[b]) return;
    int src = g_cidx[b * T_ + i];
    const uint64_t* sp = (const uint64_t*)(g_hx  + ((size_t)b * T_ + src) * C_);
    uint64_t*       dp = (uint64_t*)      (g_hxc + ((size_t)b * T_ + i)   * C_);
    dp[threadIdx.x] = sp[threadIdx.x];   // 8 bytes = 4 halfs per thread
}

// ===========================================================================
// fp16 WMMA GEMM (R16 verbatim): CTA 256x128, BK=64, 8 warps, warp tile 64x64.
// which==0 uses A0 (full M); which 1/2 use A1 (compacted x) and early-exit
// m-tiles entirely above nvalid[batch].
// ===========================================================================
#define LDH  72
#define LDC_ 132
#define NCH  12

#define G_A_SZ (256*LDH*2)
#define G_W_SZ (128*LDH*2)
#define G_BUF  (G_A_SZ + G_W_SZ)
#define SMEM_GEMM_ (2*G_BUF)

__global__ __launch_bounds__(256) void gemm_h(
    const __half* __restrict__ A0, const __half* __restrict__ A1,
    const __half* __restrict__ W0, const __half* __restrict__ W1, const __half* __restrict__ W2,
    const float* __restrict__ b0, const float* __restrict__ b1, const float* __restrict__ b2,
    __half* __restrict__ C0, __half* __restrict__ C1, __half* __restrict__ C2,
    float* __restrict__ CF)
{
    extern __shared__ char smc[];
    float* St = (float*)smc;
    const uint32_t sb = smem_u32(smc);

    const int tid = threadIdx.x;
    const int wid = tid >> 5;
    const int warp_m = wid & 3;
    const int warp_n = wid >> 2;

    const int m0 = blockIdx.x * 256;
    const int which = blockIdx.y / 6;
    const int n0 = (blockIdx.y % 6) * 128;

    if (which != 0) {
        int bb = m0 >> 11;                       // T_ = 2048
        if ((m0 & 2047) >= g_nvalid[bb]) return;
    }

    const __half* A   = (which == 0) ? A0 : A1;
    const __half* W   = (which == 0) ? W0 : (which == 1) ? W1 : W2;
    const float* bias = (which == 0) ? b0 : (which == 1) ? b1 : b2;
    __half*      Cm   = (which == 0) ? C0 : (which == 1) ? C1 : C2;

    const __half* Arow = A + (size_t)m0 * C_;
    const __half* Wrow = W + (size_t)n0 * C_;

    wmma::fragment<wmma::accumulator, 16, 16, 16, float> acc[4][4];
    #pragma unroll
    for (int i = 0; i < 4; i++)
        #pragma unroll
        for (int j = 0; j < 4; j++)
            wmma::fill_fragment(acc[i][j], 0.0f);

    auto stage = [&](int buf, int k0) {
        uint32_t Ad = sb + (buf ? (uint32_t)G_BUF : 0u);
        uint32_t Wd = Ad + (uint32_t)G_A_SZ;
        #pragma unroll
        for (int e = 0; e < 8; e++) {
            int lin = e * 256 + tid;
            int row = lin >> 3, c8 = lin & 7;
            cp16(Ad + (uint32_t)(row * LDH + c8 * 8) * 2,
                 Arow + (size_t)row * C_ + k0 + c8 * 8);
        }
        #pragma unroll
        for (int e = 0; e < 4; e++) {
            int lin = e * 256 + tid;
            int row = lin >> 3, c8 = lin & 7;
            cp16(Wd + (uint32_t)(row * LDH + c8 * 8) * 2,
                 Wrow + (size_t)row * C_ + k0 + c8 * 8);
        }
    };

    stage(0, 0);
    CP_COMMIT();

    for (int c = 0; c < NCH; c++) {
        const int b = c & 1;
        if (c < NCH - 1) { stage(b ^ 1, (c + 1) * 64); CP_COMMIT(); CP_WAIT(1); }
        else             { CP_WAIT(0); }
        __syncthreads();

        const __half* Ab = (const __half*)(smc + (b ? G_BUF : 0));
        const __half* Wb = (const __half*)((const char*)Ab + G_A_SZ);
        #pragma unroll
        for (int ks = 0; ks < 4; ks++) {
            wmma::fragment<wmma::matrix_a, 16, 16, 16, __half, wmma::row_major> af[4];
            #pragma unroll
            for (int i = 0; i < 4; i++)
                wmma::load_matrix_sync(af[i], Ab + (warp_m * 64 + i * 16) * LDH + ks * 16, LDH);
            #pragma unroll
            for (int j = 0; j < 4; j++) {
                wmma::fragment<wmma::matrix_b, 16, 16, 16, __half, wmma::col_major> bf;
                wmma::load_matrix_sync(bf, Wb + (warp_n * 64 + j * 16) * LDH + ks * 16, LDH);
                #pragma unroll
                for (int i = 0; i < 4; i++)
                    wmma::mma_sync(acc[i][j], af[i], bf, acc[i][j]);
            }
        }
        __syncthreads();
    }

    #pragma unroll
    for (int p = 0; p < 2; p++) {
        if ((warp_m >> 1) == p) {
            int lm = (warp_m & 1) * 64;
            #pragma unroll
            for (int i = 0; i < 4; i++)
                #pragma unroll
                for (int j = 0; j < 4; j++)
                    wmma::store_matrix_sync(
                        St + (lm + i * 16) * LDC_ + warp_n * 64 + j * 16,
                        acc[i][j], LDC_, wmma::mem_row_major);
        }
        __syncthreads();
        #pragma unroll
        for (int e = 0; e < 16; e++) {
            int lin = e * 256 + tid;
            int row = lin >> 5;
            int c4  = lin & 31;
            float4 v = *(const float4*)(St + row * LDC_ + c4 * 4);
            v.x += bias[n0 + c4 * 4 + 0];
            v.y += bias[n0 + c4 * 4 + 1];
            v.z += bias[n0 + c4 * 4 + 2];
            v.w += bias[n0 + c4 * 4 + 3];
            size_t grow = (size_t)(m0 + p * 128 + row) * C_ + n0 + c4 * 4;
            if (CF) {
                *(float4*)(CF + grow) = v;
            } else {
                *(__half2*)(Cm + grow + 0) = __floats2half2_rn(v.x, v.y);
                *(__half2*)(Cm + grow + 2) = __floats2half2_rn(v.z, v.w);
            }
        }
        __syncthreads();
    }
}

// ===========================================================================
// mma.sync attention, 128 q-rows per CTA via 8 WARPS (16 q-rows each) —
// per-warp register pressure identical to the proven R8 kernel, but each
// staged K/V tile now feeds 2x the compute: K/V L2 traffic halves.
// Contiguous compact K/V, positional tail mask.
// ===========================================================================
#define KLD 72

#define AOF_K0 0
#define AOF_K1 (64*KLD*2)                   //  9216
#define AOF_V0 (2*64*KLD*2)                 // 18432
#define AOF_V1 (3*64*KLD*2)                 // 27648
#define AOF_Q  (4*64*KLD*2)                 // 36864
#define ATTN_SMEM (AOF_Q + 128*KLD*2)       // 55296 -> 4 CTAs/SM w/ carveout

__global__ __launch_bounds__(256) void attn_m()
{
    extern __shared__ char smc[];
    const uint32_t sb = smem_u32(smc);

    const int tid  = threadIdx.x;
    const int w    = tid >> 5;                // 0..7: q rows w*16..+15
    const int lane = tid & 31;
    const int q4   = lane & 3;
    const int lrow = lane & 15;
    const int lc8  = (lane >> 4) * 8;

    const int t0 = blockIdx.x * 128;
    const int h  = blockIdx.y;
    const int b  = blockIdx.z;

    const __half* Qg = g_hq + (size_t)b * T_ * C_ + h * HD_;
    const __half* Kg = g_hk + (size_t)b * T_ * C_ + h * HD_;   // compact rows
    const __half* Vg = g_hv + (size_t)b * T_ * C_ + h * HD_;   // compact rows

    const int nv = g_nvalid[b];
    const int ntiles = (nv + 63) >> 6;

    auto stageKV = [&](int buf, int kt) {
        int k0 = kt * 64;
        uint32_t Kd = sb + (buf ? AOF_K1 : AOF_K0);
        uint32_t Vd = sb + (buf ? AOF_V1 : AOF_V0);
        #pragma unroll
        for (int e = 0; e < 2; e++) {             // 512 cp16 over 256 threads
            int lin = e * 256 + tid;
            int row = lin >> 3, c8 = lin & 7;
            int gi  = k0 + row;
            int src = (gi < nv) ? gi : 0;         // pure-ALU clamp, no LDG
            uint32_t off = (uint32_t)(row * KLD + c8 * 8) * 2;
            cp16(Kd + off, Kg + (size_t)src * C_ + c8 * 8);
            cp16(Vd + off, Vg + (size_t)src * C_ + c8 * 8);
        }
    };

    // prologue: 128 Q rows + first K/V tile
    #pragma unroll
    for (int e = 0; e < 4; e++) {                 // 1024 cp16 over 256 threads
        int lin = e * 256 + tid;
        int row = lin >> 3, c8 = lin & 7;
        cp16(sb + AOF_Q + (uint32_t)(row * KLD + c8 * 8) * 2,
             Qg + (size_t)(t0 + row) * C_ + c8 * 8);
    }
    stageKV(0, 0);
    CP_COMMIT();
    CP_WAIT(0);
    __syncthreads();

    uint32_t qa[4][4];
    #pragma unroll
    for (int c = 0; c < 4; c++)
        ldm4(qa[c], sb + AOF_Q + (uint32_t)((w * 16 + lrow) * KLD + c * 16 + lc8) * 2);

    float oacc[8][4];
    #pragma unroll
    for (int nb = 0; nb < 8; nb++)
        #pragma unroll
        for (int e = 0; e < 4; e++)
            oacc[nb][e] = 0.0f;

    float lsum0 = 0.0f, lsum1 = 0.0f;

    for (int kt = 0; kt < ntiles; kt++) {
        const int bb = kt & 1;
        if (kt + 1 < ntiles) { stageKV(bb ^ 1, kt + 1); CP_COMMIT(); }

        float sacc[8][4];
        #pragma unroll
        for (int nb = 0; nb < 8; nb++)
            #pragma unroll
            for (int e = 0; e < 4; e++)
                sacc[nb][e] = 0.0f;

        uint32_t kbase = sb + (bb ? AOF_K1 : AOF_K0);
        #pragma unroll
        for (int c = 0; c < 4; c++) {
            #pragma unroll
            for (int j = 0; j < 4; j++) {
                uint32_t kr[4];
                ldm4(kr, kbase + (uint32_t)((16 * j + lrow) * KLD + c * 16 + lc8) * 2);
                uint32_t bA[2] = { kr[0], kr[2] };
                uint32_t bB[2] = { kr[1], kr[3] };
                mma_f16(sacc[2 * j + 0], qa[c], bA);
                mma_f16(sacc[2 * j + 1], qa[c], bB);
            }
        }

        const int k0 = kt * 64;
        uint32_t pa[4][4];
        #pragma unroll
        for (int j = 0; j < 4; j++) {
            #pragma unroll
            for (int sub = 0; sub < 2; sub++) {
                int nb = 2 * j + sub;
                int col = k0 + nb * 8 + 2 * q4;
                float m0 = (col     < nv) ? 0.0f : -1e30f;
                float m1 = (col + 1 < nv) ? 0.0f : -1e30f;
                float p0 = __expf(fmaf(sacc[nb][0], 0.125f, m0));
                float p1 = __expf(fmaf(sacc[nb][1], 0.125f, m1));
                float p2 = __expf(fmaf(sacc[nb][2], 0.125f, m0));
                float p3 = __expf(fmaf(sacc[nb][3], 0.125f, m1));
                lsum0 += p0 + p1;
                lsum1 += p2 + p3;
                pa[j][2 * sub + 0] = pack_h2(p0, p1);
                pa[j][2 * sub + 1] = pack_h2(p2, p3);
            }
        }

        uint32_t vbase = sb + (bb ? AOF_V1 : AOF_V0);
        #pragma unroll
        for (int j = 0; j < 4; j++) {
            #pragma unroll
            for (int np = 0; np < 4; np++) {
                uint32_t vr[4];
                ldm4t(vr, vbase + (uint32_t)((16 * j + lrow) * KLD + np * 16 + lc8) * 2);
                uint32_t bA[2] = { vr[0], vr[1] };
                uint32_t bB[2] = { vr[2], vr[3] };
                mma_f16(oacc[2 * np + 0], pa[j], bA);
                mma_f16(oacc[2 * np + 1], pa[j], bB);
            }
        }

        if (kt + 1 < ntiles) CP_WAIT(0);
        __syncthreads();
    }

    lsum0 += __shfl_xor_sync(0xffffffffu, lsum0, 1);
    lsum0 += __shfl_xor_sync(0xffffffffu, lsum0, 2);
    lsum1 += __shfl_xor_sync(0xffffffffu, lsum1, 1);
    lsum1 += __shfl_xor_sync(0xffffffffu, lsum1, 2);
    float r0 = 1.0f / lsum0;
    float r1 = 1.0f / lsum1;

    __half* Yb = g_hy + (size_t)b * T_ * C_ + h * HD_;
    const int row0 = t0 + w * 16 + (lane >> 2);
    #pragma unroll
    for (int nb = 0; nb < 8; nb++) {
        int col = nb * 8 + 2 * q4;
        *(__half2*)(Yb + (size_t)row0 * C_ + col) =
            __floats2half2_rn(oacc[nb][0] * r0, oacc[nb][1] * r0);
        *(__half2*)(Yb + (size_t)(row0 + 8) * C_ + col) =
            __floats2half2_rn(oacc[nb][2] * r1, oacc[nb][3] * r1);
    }
}

// ---------------------------------------------------------------------------
extern "C" void kernel_launch(void* const* d_in, const int* in_sizes, int n_in,
                              void* d_out, int out_size)
{
    const float* x    = (const float*)d_in[0];
    const int*   mask = (const int*)  d_in[1];
    const float* Wq   = (const float*)d_in[2];
    const float* bq   = (const float*)d_in[3];
    const float* Wk   = (const float*)d_in[4];
    const float* bk   = (const float*)d_in[5];
    const float* Wv   = (const float*)d_in[6];
    const float* bv   = (const float*)d_in[7];
    const float* Wp   = (const float*)d_in[8];
    const float* bp   = (const float*)d_in[9];
    float* out = (float*)d_out;

    __half *hx, *hxc, *hq, *hk, *hv, *hy, *hwq, *hwk, *hwv, *hwp;
    cudaGetSymbolAddress((void**)&hx,  g_hx);
    cudaGetSymbolAddress((void**)&hxc, g_hxc);
    cudaGetSymbolAddress((void**)&hq,  g_hq);
    cudaGetSymbolAddress((void**)&hk,  g_hk);
    cudaGetSymbolAddress((void**)&hv,  g_hv);
    cudaGetSymbolAddress((void**)&hy,  g_hy);
    cudaGetSymbolAddress((void**)&hwq, g_hwq);
    cudaGetSymbolAddress((void**)&hwk, g_hwk);
    cudaGetSymbolAddress((void**)&hwv, g_hwv);
    cudaGetSymbolAddress((void**)&hwp, g_hwp);

    cudaFuncSetAttribute(gemm_h, cudaFuncAttributeMaxDynamicSharedMemorySize, SMEM_GEMM_);
    cudaFuncSetAttribute(attn_m, cudaFuncAttributeMaxDynamicSharedMemorySize, ATTN_SMEM);
    cudaFuncSetAttribute(attn_m, cudaFuncAttributePreferredSharedMemoryCarveout, 100);

    f2h5<<<(N4TOT_ + 255) / 256, 256>>>(x, Wq, Wk, Wv, Wp);
    scan_mask<<<B_, 128>>>(mask);
    gather_x<<<dim3(T_, B_), 192>>>();

    // Q from full hx; K/V from compacted hxc (early-exit tiles beyond nvalid)
    gemm_h<<<dim3(M_ / 256, 18), 256, SMEM_GEMM_>>>(
        hx, hxc, hwq, hwk, hwv, bq, bk, bv, hq, hk, hv, nullptr);

    attn_m<<<dim3(T_ / 128, H_, B_), 256, ATTN_SMEM>>>();

    // output projection (fp32 out, full M)
    gemm_h<<<dim3(M_ / 256, 6), 256, SMEM_GEMM_>>>(
        hy, hy, hwp, hwp, hwp, bp, bp, bp, nullptr, nullptr, nullptr, out);
}